// round 2
// baseline (speedup 1.0000x reference)
#include <cuda_runtime.h>
#include <math.h>

// GATv2 x3 + pooling. Sizes fixed by the benchmark instance.
namespace {
constexpr int NN = 50000;          // nodes
constexpr int NE = 800000;         // edges (before self loops)
constexpr int ET = NE + NN;        // edges incl. self loops
constexpr int NG = 16;             // graphs
constexpr int TB = 256;            // threads per block
}

// ---------------- scratch (device globals; no allocation allowed) ----------
__device__ __align__(16) float g_xl[(size_t)NN * 128];
__device__ __align__(16) float g_xr[(size_t)NN * 128];
__device__ __align__(16) float g_agg[(size_t)NN * 128];
__device__ __align__(16) float g_h[(size_t)NN * 128];
__device__ float g_ex[(size_t)ET * 2];
__device__ float g_smax[NN * 2];
__device__ float g_den[NN * 2];
__device__ float g_psum[NG * 32];
__device__ float g_pmax[NG * 32];
__device__ float g_cnt[NG];

__device__ __forceinline__ void atomicMaxF(float* a, float v) {
    if (v >= 0.f) atomicMax((int*)a, __float_as_int(v));
    else          atomicMin((unsigned int*)a, __float_as_uint(v));
}

// ---------------- init -----------------------------------------------------
__global__ void init_layer_kernel(int nCT, int nH) {
    int i = blockIdx.x * blockDim.x + threadIdx.x;
    if (i < nCT) g_agg[i] = 0.f;
    if (i < nH) { g_smax[i] = -INFINITY; g_den[i] = 0.f; }
}

// ---------------- dense: Y = X @ W + B  (per-block SMEM-staged W) ----------
template<int IN, int OUT, int KT>
__global__ void linear_kernel(const float* __restrict__ X,
                              const float* __restrict__ W,
                              const float* __restrict__ B,
                              float* __restrict__ Y) {
    __shared__ float Ws[KT * OUT];
    constexpr int NSTR = TB / OUT;     // node groups in flight
    constexpr int NPB  = 16;           // nodes per block (divides NN)
    constexpr int MACC = NPB / NSTR;
    const int nb = blockIdx.x * NPB;
    const int o  = threadIdx.x % OUT;
    const int nt = threadIdx.x / OUT;

    float acc[MACC];
    const float bo = B[o];
#pragma unroll
    for (int m = 0; m < MACC; m++) acc[m] = bo;

    for (int kt = 0; kt < IN; kt += KT) {
        __syncthreads();
        for (int i = threadIdx.x; i < KT * OUT; i += TB)
            Ws[i] = W[(size_t)(kt + i / OUT) * OUT + (i % OUT)];
        __syncthreads();
#pragma unroll
        for (int m = 0; m < MACC; m++) {
            const int node = nb + nt + m * NSTR;
            const float* xp = X + (size_t)node * IN + kt;
#pragma unroll
            for (int k = 0; k < KT; k++)
                acc[m] += xp[k] * Ws[k * OUT + o];
        }
    }
#pragma unroll
    for (int m = 0; m < MACC; m++) {
        const int node = nb + nt + m * NSTR;
        Y[(size_t)node * OUT + o] = acc[m];
    }
}

// ---------------- edge pass 1: score + segment max -------------------------
// one warp per edge; CT channels split over 32 lanes (float4 when CT==128)
template<int CT, int H>
__global__ void edge_score_kernel(const int* __restrict__ ei,
                                  const float* __restrict__ att) {
    const int e = (blockIdx.x * blockDim.x + threadIdx.x) >> 5;
    if (e >= ET) return;
    const int lane = threadIdx.x & 31;
    int src, dst;
    if (e < NE) { src = ei[e]; dst = ei[NE + e]; }
    else        { src = e - NE; dst = src; }

    float part;
    if (CT == 128) {
        const float4 a = *(const float4*)(g_xl + (size_t)src * CT + lane * 4);
        const float4 b = *(const float4*)(g_xr + (size_t)dst * CT + lane * 4);
        const float4 w = *(const float4*)(att + lane * 4);
        float t;
        part = 0.f;
        t = a.x + b.x; t = t > 0.f ? t : 0.2f * t; part += t * w.x;
        t = a.y + b.y; t = t > 0.f ? t : 0.2f * t; part += t * w.y;
        t = a.z + b.z; t = t > 0.f ? t : 0.2f * t; part += t * w.z;
        t = a.w + b.w; t = t > 0.f ? t : 0.2f * t; part += t * w.w;
    } else {
        float t = g_xl[(size_t)src * CT + lane] + g_xr[(size_t)dst * CT + lane];
        t = t > 0.f ? t : 0.2f * t;
        part = t * att[lane];
    }
    constexpr int SEG = 32 / H;   // lanes per head
#pragma unroll
    for (int off = SEG / 2; off > 0; off >>= 1)
        part += __shfl_down_sync(0xffffffffu, part, off);
    if ((lane & (SEG - 1)) == 0) {
        const int h = lane / SEG;
        g_ex[(size_t)e * H + h] = part;
        atomicMaxF(&g_smax[dst * H + h], part);
    }
}

// ---------------- edge pass 2: exp + segment sum ---------------------------
template<int H>
__global__ void edge_exp_kernel(const int* __restrict__ ei) {
    const int i = blockIdx.x * blockDim.x + threadIdx.x;
    if (i >= ET * H) return;
    const int e = i / H, h = i - e * H;
    const int dst = (e < NE) ? ei[NE + e] : e - NE;
    const float ex = __expf(g_ex[i] - g_smax[dst * H + h]);
    g_ex[i] = ex;
    atomicAdd(&g_den[dst * H + h], ex);
}

// ---------------- edge pass 3: weighted scatter ----------------------------
template<int CT, int H>
__global__ void edge_agg_kernel(const int* __restrict__ ei) {
    const int e = (blockIdx.x * blockDim.x + threadIdx.x) >> 5;
    if (e >= ET) return;
    const int lane = threadIdx.x & 31;
    int src, dst;
    if (e < NE) { src = ei[e]; dst = ei[NE + e]; }
    else        { src = e - NE; dst = src; }

    constexpr int SEG = 32 / H;
    const int h = lane / SEG;
    const float alpha = g_ex[(size_t)e * H + h] / (g_den[dst * H + h] + 1e-16f);

    if (CT == 128) {
        const float4 a = *(const float4*)(g_xl + (size_t)src * CT + lane * 4);
        float* o = g_agg + (size_t)dst * CT + lane * 4;
        atomicAdd(o + 0, alpha * a.x);
        atomicAdd(o + 1, alpha * a.y);
        atomicAdd(o + 2, alpha * a.z);
        atomicAdd(o + 3, alpha * a.w);
    } else {
        atomicAdd(g_agg + (size_t)dst * CT + lane,
                  alpha * g_xl[(size_t)src * CT + lane]);
    }
}

// ---------------- bias + ELU ----------------------------------------------
template<int CT>
__global__ void finalize_kernel(const float* __restrict__ B, float* __restrict__ Hout) {
    const int i = blockIdx.x * blockDim.x + threadIdx.x;
    if (i >= NN * CT) return;
    const float v = g_agg[i] + B[i % CT];
    Hout[i] = v > 0.f ? v : expm1f(v);
}

// ---------------- pooling --------------------------------------------------
__global__ void pool_init_kernel() {
    int i = blockIdx.x * blockDim.x + threadIdx.x;
    if (i < NG * 32) { g_psum[i] = 0.f; g_pmax[i] = -INFINITY; }
    if (i < NG) g_cnt[i] = 0.f;
}

__global__ void pool_accum_kernel(const float* __restrict__ h,
                                  const int* __restrict__ batch) {
    const int i = blockIdx.x * blockDim.x + threadIdx.x;
    if (i >= NN * 32) return;
    const int node = i >> 5, c = i & 31;
    const int g = batch[node];
    const float v = h[i];
    atomicAdd(&g_psum[g * 32 + c], v);
    atomicMaxF(&g_pmax[g * 32 + c], v);
    if (c == 0) atomicAdd(&g_cnt[g], 1.f);
}

__global__ void pool_final_kernel(float* __restrict__ out) {
    const int i = blockIdx.x * blockDim.x + threadIdx.x;
    if (i >= NG * 64) return;
    const int g = i / 64, c = i % 64;
    out[i] = (c < 32) ? g_psum[g * 32 + c] / g_cnt[g]
                      : g_pmax[g * 32 + (c - 32)];
}

// ---------------- launch ---------------------------------------------------
static inline int gridFor(long long n) { return (int)((n + TB - 1) / TB); }

extern "C" void kernel_launch(void* const* d_in, const int* in_sizes, int n_in,
                              void* d_out, int out_size) {
    const float* x     = (const float*)d_in[0];
    const int*   ei    = (const int*)d_in[1];
    const int*   batch = (const int*)d_in[2];
    const float *Wl1=(const float*)d_in[3],  *bl1=(const float*)d_in[4];
    const float *Wr1=(const float*)d_in[5],  *br1=(const float*)d_in[6];
    const float *att1=(const float*)d_in[7], *b1=(const float*)d_in[8];
    const float *Wl2=(const float*)d_in[9],  *bl2=(const float*)d_in[10];
    const float *Wr2=(const float*)d_in[11], *br2=(const float*)d_in[12];
    const float *att2=(const float*)d_in[13],*b2=(const float*)d_in[14];
    const float *Wl3=(const float*)d_in[15], *bl3=(const float*)d_in[16];
    const float *Wr3=(const float*)d_in[17], *br3=(const float*)d_in[18];
    const float *att3=(const float*)d_in[19],*b3=(const float*)d_in[20];

    float *p_xl, *p_xr, *p_h;
    cudaGetSymbolAddress((void**)&p_xl, g_xl);
    cudaGetSymbolAddress((void**)&p_xr, g_xr);
    cudaGetSymbolAddress((void**)&p_h,  g_h);

    const int gNodes128 = gridFor((long long)NN * 128);
    const int gNodes32  = gridFor((long long)NN * 32);
    const int gEdgeWarp = gridFor((long long)ET * 32);
    const int gLin      = NN / 16;

    // ---- layer 1: 8 -> 128 (H=2, C=64), concat
    init_layer_kernel<<<gNodes128, TB>>>(NN * 128, NN * 2);
    linear_kernel<8, 128, 8><<<gLin, TB>>>(x, Wl1, bl1, p_xl);
    linear_kernel<8, 128, 8><<<gLin, TB>>>(x, Wr1, br1, p_xr);
    edge_score_kernel<128, 2><<<gEdgeWarp, TB>>>(ei, att1);
    edge_exp_kernel<2><<<gridFor((long long)ET * 2), TB>>>(ei);
    edge_agg_kernel<128, 2><<<gEdgeWarp, TB>>>(ei);
    finalize_kernel<128><<<gNodes128, TB>>>(b1, p_h);

    // ---- layer 2: 128 -> 128 (H=2, C=64), concat
    init_layer_kernel<<<gNodes128, TB>>>(NN * 128, NN * 2);
    linear_kernel<128, 128, 64><<<gLin, TB>>>(p_h, Wl2, bl2, p_xl);
    linear_kernel<128, 128, 64><<<gLin, TB>>>(p_h, Wr2, br2, p_xr);
    edge_score_kernel<128, 2><<<gEdgeWarp, TB>>>(ei, att2);
    edge_exp_kernel<2><<<gridFor((long long)ET * 2), TB>>>(ei);
    edge_agg_kernel<128, 2><<<gEdgeWarp, TB>>>(ei);
    finalize_kernel<128><<<gNodes128, TB>>>(b2, p_h);

    // ---- layer 3: 128 -> 32 (H=1, C=32), mean over heads (=identity)
    init_layer_kernel<<<gNodes32, TB>>>(NN * 32, NN);
    linear_kernel<128, 32, 64><<<gLin, TB>>>(p_h, Wl3, bl3, p_xl);
    linear_kernel<128, 32, 64><<<gLin, TB>>>(p_h, Wr3, br3, p_xr);
    edge_score_kernel<32, 1><<<gEdgeWarp, TB>>>(ei, att3);
    edge_exp_kernel<1><<<gridFor((long long)ET), TB>>>(ei);
    edge_agg_kernel<32, 1><<<gEdgeWarp, TB>>>(ei);
    finalize_kernel<32><<<gNodes32, TB>>>(b3, p_h);

    // ---- pooling: per-graph mean & max -> [16, 64]
    pool_init_kernel<<<gridFor(NG * 32), TB>>>();
    pool_accum_kernel<<<gNodes32, TB>>>(p_h, batch);
    pool_final_kernel<<<gridFor(NG * 64), TB>>>((float*)d_out);
}

// round 3
// speedup vs baseline: 1.2746x; 1.2746x over previous
#include <cuda_runtime.h>
#include <math.h>

// GATv2 x3 + pooling. Sizes fixed by the benchmark instance.
namespace {
constexpr int NN = 50000;          // nodes
constexpr int NE = 800000;         // edges (before self loops)
constexpr int ET = NE + NN;        // edges incl. self loops
constexpr int NG = 16;             // graphs
constexpr int TB = 256;            // threads per block
}

// ---------------- scratch (device globals; no allocation allowed) ----------
__device__ __align__(16) float g_xl[(size_t)NN * 128];
__device__ __align__(16) float g_xr[(size_t)NN * 128];
__device__ __align__(16) float g_agg[(size_t)NN * 128];
__device__ __align__(16) float g_h[(size_t)NN * 128];
__device__ __align__(8)  float g_ex[(size_t)ET * 2];
__device__ __align__(8)  float g_smax[NN * 2];
__device__ __align__(8)  float g_den[NN * 2];
__device__ float g_psum[NG * 32];
__device__ float g_pmax[NG * 32];
__device__ float g_cnt[NG];

__device__ __forceinline__ void atomicMaxF(float* a, float v) {
    if (v >= 0.f) atomicMax((int*)a, __float_as_int(v));
    else          atomicMin((unsigned int*)a, __float_as_uint(v));
}

__device__ __forceinline__ void redAdd4(float* p, float a, float b, float c, float d) {
    asm volatile("red.global.add.v4.f32 [%0], {%1,%2,%3,%4};"
                 :: "l"(p), "f"(a), "f"(b), "f"(c), "f"(d) : "memory");
}
__device__ __forceinline__ void redAdd2(float* p, float a, float b) {
    asm volatile("red.global.add.v2.f32 [%0], {%1,%2};"
                 :: "l"(p), "f"(a), "f"(b) : "memory");
}

// ---------------- init -----------------------------------------------------
__global__ void init_layer_kernel(int nCT, int nH) {
    int i = blockIdx.x * blockDim.x + threadIdx.x;
    if (i < nCT) g_agg[i] = 0.f;
    if (i < nH) { g_smax[i] = -INFINITY; g_den[i] = 0.f; }
}

// ---------------- dense: Y = X @ W + B  (per-block SMEM-staged W) ----------
template<int IN, int OUT, int KT>
__global__ void linear_kernel(const float* __restrict__ X,
                              const float* __restrict__ W,
                              const float* __restrict__ B,
                              float* __restrict__ Y) {
    __shared__ float Ws[KT * OUT];
    constexpr int NSTR = TB / OUT;     // node groups in flight
    constexpr int NPB  = 16;           // nodes per block (divides NN)
    constexpr int MACC = NPB / NSTR;
    const int nb = blockIdx.x * NPB;
    const int o  = threadIdx.x % OUT;
    const int nt = threadIdx.x / OUT;

    float acc[MACC];
    const float bo = B[o];
#pragma unroll
    for (int m = 0; m < MACC; m++) acc[m] = bo;

    for (int kt = 0; kt < IN; kt += KT) {
        __syncthreads();
        for (int i = threadIdx.x; i < KT * OUT; i += TB)
            Ws[i] = W[(size_t)(kt + i / OUT) * OUT + (i % OUT)];
        __syncthreads();
#pragma unroll
        for (int m = 0; m < MACC; m++) {
            const int node = nb + nt + m * NSTR;
            const float* xp = X + (size_t)node * IN + kt;
#pragma unroll
            for (int k = 0; k < KT; k++)
                acc[m] += xp[k] * Ws[k * OUT + o];
        }
    }
#pragma unroll
    for (int m = 0; m < MACC; m++) {
        const int node = nb + nt + m * NSTR;
        Y[(size_t)node * OUT + o] = acc[m];
    }
}

// ---------------- edge pass 1 (CT=128, H=2): score + segment max -----------
__global__ void edge_score128_kernel(const int* __restrict__ ei,
                                     const float* __restrict__ att) {
    const int e = (blockIdx.x * blockDim.x + threadIdx.x) >> 5;
    if (e >= ET) return;
    const int lane = threadIdx.x & 31;
    int src, dst;
    if (e < NE) { src = ei[e]; dst = ei[NE + e]; }
    else        { src = e - NE; dst = src; }

    const float4 a = *(const float4*)(g_xl + (size_t)src * 128 + lane * 4);
    const float4 b = *(const float4*)(g_xr + (size_t)dst * 128 + lane * 4);
    const float4 w = *(const float4*)(att + lane * 4);
    float t, part = 0.f;
    t = a.x + b.x; t = t > 0.f ? t : 0.2f * t; part += t * w.x;
    t = a.y + b.y; t = t > 0.f ? t : 0.2f * t; part += t * w.y;
    t = a.z + b.z; t = t > 0.f ? t : 0.2f * t; part += t * w.z;
    t = a.w + b.w; t = t > 0.f ? t : 0.2f * t; part += t * w.w;

#pragma unroll
    for (int off = 8; off > 0; off >>= 1)
        part += __shfl_down_sync(0xffffffffu, part, off);
    if ((lane & 15) == 0) {
        const int h = lane >> 4;
        g_ex[(size_t)e * 2 + h] = part;
        atomicMaxF(&g_smax[dst * 2 + h], part);
    }
}

// ---------------- edge pass 1 (CT=32, H=1): 4 edges per warp ---------------
__global__ void edge_score32_kernel(const int* __restrict__ ei,
                                    const float* __restrict__ att) {
    const int warp = (blockIdx.x * blockDim.x + threadIdx.x) >> 5;
    const int lane = threadIdx.x & 31;
    const int e = warp * 4 + (lane >> 3);
    if (e >= ET) return;
    const int c8 = lane & 7;            // channel group (4 floats each)
    int src, dst;
    if (e < NE) { src = ei[e]; dst = ei[NE + e]; }
    else        { src = e - NE; dst = src; }

    const float4 a = *(const float4*)(g_xl + (size_t)src * 32 + c8 * 4);
    const float4 b = *(const float4*)(g_xr + (size_t)dst * 32 + c8 * 4);
    const float4 w = *(const float4*)(att + c8 * 4);
    float t, part = 0.f;
    t = a.x + b.x; t = t > 0.f ? t : 0.2f * t; part += t * w.x;
    t = a.y + b.y; t = t > 0.f ? t : 0.2f * t; part += t * w.y;
    t = a.z + b.z; t = t > 0.f ? t : 0.2f * t; part += t * w.z;
    t = a.w + b.w; t = t > 0.f ? t : 0.2f * t; part += t * w.w;

    part += __shfl_down_sync(0xffffffffu, part, 4);
    part += __shfl_down_sync(0xffffffffu, part, 2);
    part += __shfl_down_sync(0xffffffffu, part, 1);
    if (c8 == 0) {
        g_ex[(size_t)e * 2] = part;       // H=1: slot 0 only
        atomicMaxF(&g_smax[dst * 2], part);
    }
}

// ---------------- edge pass 2: exp + segment sum ---------------------------
__global__ void edge_exp2_kernel(const int* __restrict__ ei) {   // H=2
    const int e = blockIdx.x * blockDim.x + threadIdx.x;
    if (e >= ET) return;
    const int dst = (e < NE) ? ei[NE + e] : e - NE;
    const float2 sc = *(const float2*)(g_ex + (size_t)e * 2);
    const float2 mx = *(const float2*)(g_smax + dst * 2);
    const float ex0 = __expf(sc.x - mx.x);
    const float ex1 = __expf(sc.y - mx.y);
    *(float2*)(g_ex + (size_t)e * 2) = make_float2(ex0, ex1);
    redAdd2(&g_den[dst * 2], ex0, ex1);
}

__global__ void edge_exp1_kernel(const int* __restrict__ ei) {   // H=1
    const int e = blockIdx.x * blockDim.x + threadIdx.x;
    if (e >= ET) return;
    const int dst = (e < NE) ? ei[NE + e] : e - NE;
    const float ex = __expf(g_ex[(size_t)e * 2] - g_smax[dst * 2]);
    g_ex[(size_t)e * 2] = ex;
    atomicAdd(&g_den[dst * 2], ex);
}

// ---------------- edge pass 3 (CT=128, H=2): weighted scatter --------------
__global__ void edge_agg128_kernel(const int* __restrict__ ei) {
    const int e = (blockIdx.x * blockDim.x + threadIdx.x) >> 5;
    if (e >= ET) return;
    const int lane = threadIdx.x & 31;
    int src, dst;
    if (e < NE) { src = ei[e]; dst = ei[NE + e]; }
    else        { src = e - NE; dst = src; }

    const int h = lane >> 4;
    const float alpha = g_ex[(size_t)e * 2 + h] / (g_den[dst * 2 + h] + 1e-16f);

    const float4 a = *(const float4*)(g_xl + (size_t)src * 128 + lane * 4);
    redAdd4(g_agg + (size_t)dst * 128 + lane * 4,
            alpha * a.x, alpha * a.y, alpha * a.z, alpha * a.w);
}

// ---------------- edge pass 3 (CT=32, H=1): 4 edges per warp ---------------
__global__ void edge_agg32_kernel(const int* __restrict__ ei) {
    const int warp = (blockIdx.x * blockDim.x + threadIdx.x) >> 5;
    const int lane = threadIdx.x & 31;
    const int e = warp * 4 + (lane >> 3);
    if (e >= ET) return;
    const int c8 = lane & 7;
    int src, dst;
    if (e < NE) { src = ei[e]; dst = ei[NE + e]; }
    else        { src = e - NE; dst = src; }

    const float alpha = g_ex[(size_t)e * 2] / (g_den[dst * 2] + 1e-16f);
    const float4 a = *(const float4*)(g_xl + (size_t)src * 32 + c8 * 4);
    redAdd4(g_agg + (size_t)dst * 32 + c8 * 4,
            alpha * a.x, alpha * a.y, alpha * a.z, alpha * a.w);
}

// ---------------- bias + ELU ----------------------------------------------
template<int CT>
__global__ void finalize_kernel(const float* __restrict__ B, float* __restrict__ Hout) {
    const int i = blockIdx.x * blockDim.x + threadIdx.x;
    if (i >= NN * CT) return;
    const float v = g_agg[i] + B[i % CT];
    Hout[i] = v > 0.f ? v : expm1f(v);
}

// ---------------- pooling --------------------------------------------------
__global__ void pool_init_kernel() {
    int i = blockIdx.x * blockDim.x + threadIdx.x;
    if (i < NG * 32) { g_psum[i] = 0.f; g_pmax[i] = -INFINITY; }
    if (i < NG) g_cnt[i] = 0.f;
}

__global__ void pool_accum_kernel(const float* __restrict__ h,
                                  const int* __restrict__ batch) {
    const int i = blockIdx.x * blockDim.x + threadIdx.x;
    if (i >= NN * 32) return;
    const int node = i >> 5, c = i & 31;
    const int g = batch[node];
    const float v = h[i];
    atomicAdd(&g_psum[g * 32 + c], v);
    atomicMaxF(&g_pmax[g * 32 + c], v);
    if (c == 0) atomicAdd(&g_cnt[g], 1.f);
}

__global__ void pool_final_kernel(float* __restrict__ out) {
    const int i = blockIdx.x * blockDim.x + threadIdx.x;
    if (i >= NG * 64) return;
    const int g = i / 64, c = i % 64;
    out[i] = (c < 32) ? g_psum[g * 32 + c] / g_cnt[g]
                      : g_pmax[g * 32 + (c - 32)];
}

// ---------------- launch ---------------------------------------------------
static inline int gridFor(long long n) { return (int)((n + TB - 1) / TB); }

extern "C" void kernel_launch(void* const* d_in, const int* in_sizes, int n_in,
                              void* d_out, int out_size) {
    const float* x     = (const float*)d_in[0];
    const int*   ei    = (const int*)d_in[1];
    const int*   batch = (const int*)d_in[2];
    const float *Wl1=(const float*)d_in[3],  *bl1=(const float*)d_in[4];
    const float *Wr1=(const float*)d_in[5],  *br1=(const float*)d_in[6];
    const float *att1=(const float*)d_in[7], *b1=(const float*)d_in[8];
    const float *Wl2=(const float*)d_in[9],  *bl2=(const float*)d_in[10];
    const float *Wr2=(const float*)d_in[11], *br2=(const float*)d_in[12];
    const float *att2=(const float*)d_in[13],*b2=(const float*)d_in[14];
    const float *Wl3=(const float*)d_in[15], *bl3=(const float*)d_in[16];
    const float *Wr3=(const float*)d_in[17], *br3=(const float*)d_in[18];
    const float *att3=(const float*)d_in[19],*b3=(const float*)d_in[20];

    float *p_xl, *p_xr, *p_h;
    cudaGetSymbolAddress((void**)&p_xl, g_xl);
    cudaGetSymbolAddress((void**)&p_xr, g_xr);
    cudaGetSymbolAddress((void**)&p_h,  g_h);

    const int gNodes128 = gridFor((long long)NN * 128);
    const int gNodes32  = gridFor((long long)NN * 32);
    const int gEdgeWarp = gridFor((long long)ET * 32);
    const int gEdgeQ    = gridFor((long long)((ET + 3) / 4) * 32);
    const int gEdgeTh   = gridFor((long long)ET);
    const int gLin      = NN / 16;

    // ---- layer 1: 8 -> 128 (H=2, C=64), concat
    init_layer_kernel<<<gNodes128, TB>>>(NN * 128, NN * 2);
    linear_kernel<8, 128, 8><<<gLin, TB>>>(x, Wl1, bl1, p_xl);
    linear_kernel<8, 128, 8><<<gLin, TB>>>(x, Wr1, br1, p_xr);
    edge_score128_kernel<<<gEdgeWarp, TB>>>(ei, att1);
    edge_exp2_kernel<<<gEdgeTh, TB>>>(ei);
    edge_agg128_kernel<<<gEdgeWarp, TB>>>(ei);
    finalize_kernel<128><<<gNodes128, TB>>>(b1, p_h);

    // ---- layer 2: 128 -> 128 (H=2, C=64), concat
    init_layer_kernel<<<gNodes128, TB>>>(NN * 128, NN * 2);
    linear_kernel<128, 128, 64><<<gLin, TB>>>(p_h, Wl2, bl2, p_xl);
    linear_kernel<128, 128, 64><<<gLin, TB>>>(p_h, Wr2, br2, p_xr);
    edge_score128_kernel<<<gEdgeWarp, TB>>>(ei, att2);
    edge_exp2_kernel<<<gEdgeTh, TB>>>(ei);
    edge_agg128_kernel<<<gEdgeWarp, TB>>>(ei);
    finalize_kernel<128><<<gNodes128, TB>>>(b2, p_h);

    // ---- layer 3: 128 -> 32 (H=1, C=32), head-mean (=identity)
    init_layer_kernel<<<gNodes32, TB>>>(NN * 32, NN * 2);
    linear_kernel<128, 32, 64><<<gLin, TB>>>(p_h, Wl3, bl3, p_xl);
    linear_kernel<128, 32, 64><<<gLin, TB>>>(p_h, Wr3, br3, p_xr);
    edge_score32_kernel<<<gEdgeQ, TB>>>(ei, att3);
    edge_exp1_kernel<<<gEdgeTh, TB>>>(ei);
    edge_agg32_kernel<<<gEdgeQ, TB>>>(ei);
    finalize_kernel<32><<<gNodes32, TB>>>(b3, p_h);

    // ---- pooling: per-graph mean & max -> [16, 64]
    pool_init_kernel<<<gridFor(NG * 32), TB>>>();
    pool_accum_kernel<<<gNodes32, TB>>>(p_h, batch);
    pool_final_kernel<<<gridFor(NG * 64), TB>>>((float*)d_out);
}

// round 4
// speedup vs baseline: 1.6858x; 1.3226x over previous
#include <cuda_runtime.h>
#include <math.h>

// GATv2 x3 + pooling, CSR + online-softmax fused edge pass.
namespace {
constexpr int NN = 50000;          // nodes
constexpr int NE = 800000;         // edges (before self loops)
constexpr int ET = NE + NN;        // edges incl. self loops
constexpr int NG = 16;             // graphs
constexpr int TB = 256;            // threads per block
}

// ---------------- scratch (device globals; no allocation allowed) ----------
__device__ __align__(16) float g_xl[(size_t)NN * 128];
__device__ __align__(16) float g_xr[(size_t)NN * 128];
__device__ __align__(16) float g_h[(size_t)NN * 128];
__device__ int g_deg[NN];
__device__ int g_rowptr[NN + 1];
__device__ int g_cur[NN];
__device__ int g_csrc[ET];
__device__ float g_psum[NG * 32];
__device__ float g_pmax[NG * 32];
__device__ float g_cntf[NG];

__device__ __forceinline__ void atomicMaxF(float* a, float v) {
    if (v >= 0.f) atomicMax((int*)a, __float_as_int(v));
    else          atomicMin((unsigned int*)a, __float_as_uint(v));
}

// ---------------- CSR build ------------------------------------------------
__global__ void deg_init_kernel() {
    int i = blockIdx.x * blockDim.x + threadIdx.x;
    if (i < NN) g_deg[i] = 1;            // self loop pre-counted
}

__global__ void deg_count_kernel(const int* __restrict__ ei) {
    int e = blockIdx.x * blockDim.x + threadIdx.x;
    if (e < NE) atomicAdd(&g_deg[ei[NE + e]], 1);
}

__global__ void scan_kernel() {          // single block, 1024 threads
    __shared__ int part[1024];
    const int tid = threadIdx.x;
    const int chunk = (NN + 1023) / 1024;
    const int beg = tid * chunk;
    const int end = min(beg + chunk, NN);
    int s = 0;
    for (int i = beg; i < end; i++) s += g_deg[i];
    part[tid] = s;
    __syncthreads();
    if (tid == 0) {
        int run = 0;
        for (int i = 0; i < 1024; i++) { int t = part[i]; part[i] = run; run += t; }
    }
    __syncthreads();
    int run = part[tid];
    for (int i = beg; i < end; i++) {
        g_rowptr[i] = run;
        g_cur[i] = run;
        run += g_deg[i];
    }
    if (tid == 0) g_rowptr[NN] = ET;
}

__global__ void fill_kernel(const int* __restrict__ ei) {
    int e = blockIdx.x * blockDim.x + threadIdx.x;
    if (e >= ET) return;
    int src, dst;
    if (e < NE) { src = ei[e]; dst = ei[NE + e]; }
    else        { src = e - NE; dst = src; }
    int pos = atomicAdd(&g_cur[dst], 1);
    g_csrc[pos] = src;
}

// ---------------- dense: Y = X @ W + B  (per-block SMEM-staged W) ----------
template<int IN, int OUT, int KT>
__global__ void linear_kernel(const float* __restrict__ X,
                              const float* __restrict__ W,
                              const float* __restrict__ B,
                              float* __restrict__ Y) {
    __shared__ float Ws[KT * OUT];
    constexpr int NSTR = TB / OUT;
    constexpr int NPB  = 16;
    constexpr int MACC = NPB / NSTR;
    const int nb = blockIdx.x * NPB;
    const int o  = threadIdx.x % OUT;
    const int nt = threadIdx.x / OUT;

    float acc[MACC];
    const float bo = B[o];
#pragma unroll
    for (int m = 0; m < MACC; m++) acc[m] = bo;

    for (int kt = 0; kt < IN; kt += KT) {
        __syncthreads();
        for (int i = threadIdx.x; i < KT * OUT; i += TB)
            Ws[i] = W[(size_t)(kt + i / OUT) * OUT + (i % OUT)];
        __syncthreads();
#pragma unroll
        for (int m = 0; m < MACC; m++) {
            const int node = nb + nt + m * NSTR;
            const float* xp = X + (size_t)node * IN + kt;
#pragma unroll
            for (int k = 0; k < KT; k++)
                acc[m] += xp[k] * Ws[k * OUT + o];
        }
    }
#pragma unroll
    for (int m = 0; m < MACC; m++) {
        const int node = nb + nt + m * NSTR;
        Y[(size_t)node * OUT + o] = acc[m];
    }
}

// ---------------- fused GATv2 edge pass (CT=128, H=2), warp per dst --------
// online softmax over incoming edges; epilogue = bias + ELU
__global__ void gat_fused128_kernel(const float* __restrict__ att,
                                    const float* __restrict__ B,
                                    float* __restrict__ out) {
    const int node = (blockIdx.x * blockDim.x + threadIdx.x) >> 5;
    if (node >= NN) return;
    const int lane = threadIdx.x & 31;

    const float4 xrv  = *(const float4*)(g_xr + (size_t)node * 128 + lane * 4);
    const float4 attv = *(const float4*)(att + lane * 4);

    int p  = g_rowptr[node];
    const int pe = g_rowptr[node + 1];

    float m = -INFINITY, d = 0.f;
    float4 acc = make_float4(0.f, 0.f, 0.f, 0.f);

    int src = g_csrc[p];
    while (p < pe) {
        const int src_n = (p + 1 < pe) ? g_csrc[p + 1] : 0;
        const float4 a = *(const float4*)(g_xl + (size_t)src * 128 + lane * 4);

        float t, part = 0.f;
        t = a.x + xrv.x; t = t > 0.f ? t : 0.2f * t; part += t * attv.x;
        t = a.y + xrv.y; t = t > 0.f ? t : 0.2f * t; part += t * attv.y;
        t = a.z + xrv.z; t = t > 0.f ? t : 0.2f * t; part += t * attv.z;
        t = a.w + xrv.w; t = t > 0.f ? t : 0.2f * t; part += t * attv.w;
        // reduce within each 16-lane half (head); xor keeps lanes inside half
        part += __shfl_xor_sync(0xffffffffu, part, 1);
        part += __shfl_xor_sync(0xffffffffu, part, 2);
        part += __shfl_xor_sync(0xffffffffu, part, 4);
        part += __shfl_xor_sync(0xffffffffu, part, 8);

        const float nm = fmaxf(m, part);
        const float sc = __expf(m - nm);
        const float w  = __expf(part - nm);
        d = d * sc + w;
        acc.x = acc.x * sc + w * a.x;
        acc.y = acc.y * sc + w * a.y;
        acc.z = acc.z * sc + w * a.z;
        acc.w = acc.w * sc + w * a.w;
        m = nm;
        src = src_n;
        ++p;
    }

    const float inv = 1.f / (d + 1e-16f);
    const float4 bv = *(const float4*)(B + lane * 4);
    float4 o;
    o.x = acc.x * inv + bv.x; o.x = o.x > 0.f ? o.x : expm1f(o.x);
    o.y = acc.y * inv + bv.y; o.y = o.y > 0.f ? o.y : expm1f(o.y);
    o.z = acc.z * inv + bv.z; o.z = o.z > 0.f ? o.z : expm1f(o.z);
    o.w = acc.w * inv + bv.w; o.w = o.w > 0.f ? o.w : expm1f(o.w);
    *(float4*)(out + (size_t)node * 128 + lane * 4) = o;
}

// ---------------- fused GATv2 edge pass (CT=32, H=1), warp per dst ---------
__global__ void gat_fused32_kernel(const float* __restrict__ att,
                                   const float* __restrict__ B,
                                   float* __restrict__ out) {
    const int node = (blockIdx.x * blockDim.x + threadIdx.x) >> 5;
    if (node >= NN) return;
    const int lane = threadIdx.x & 31;

    const float xrv  = g_xr[(size_t)node * 32 + lane];
    const float attv = att[lane];

    int p  = g_rowptr[node];
    const int pe = g_rowptr[node + 1];

    float m = -INFINITY, d = 0.f, acc = 0.f;

    int src = g_csrc[p];
    while (p < pe) {
        const int src_n = (p + 1 < pe) ? g_csrc[p + 1] : 0;
        const float a = g_xl[(size_t)src * 32 + lane];

        float t = a + xrv;
        t = t > 0.f ? t : 0.2f * t;
        float part = t * attv;
        part += __shfl_xor_sync(0xffffffffu, part, 1);
        part += __shfl_xor_sync(0xffffffffu, part, 2);
        part += __shfl_xor_sync(0xffffffffu, part, 4);
        part += __shfl_xor_sync(0xffffffffu, part, 8);
        part += __shfl_xor_sync(0xffffffffu, part, 16);

        const float nm = fmaxf(m, part);
        const float sc = __expf(m - nm);
        const float w  = __expf(part - nm);
        d = d * sc + w;
        acc = acc * sc + w * a;
        m = nm;
        src = src_n;
        ++p;
    }

    float o = acc / (d + 1e-16f) + B[lane];
    o = o > 0.f ? o : expm1f(o);
    out[(size_t)node * 32 + lane] = o;
}

// ---------------- pooling --------------------------------------------------
__global__ void pool_init_kernel() {
    int i = blockIdx.x * blockDim.x + threadIdx.x;
    if (i < NG * 32) { g_psum[i] = 0.f; g_pmax[i] = -INFINITY; }
    if (i < NG) g_cntf[i] = 0.f;
}

__global__ void pool_accum_kernel(const float* __restrict__ h,
                                  const int* __restrict__ batch) {
    const int i = blockIdx.x * blockDim.x + threadIdx.x;
    if (i >= NN * 32) return;
    const int node = i >> 5, c = i & 31;
    const int g = batch[node];
    const float v = h[i];
    atomicAdd(&g_psum[g * 32 + c], v);
    atomicMaxF(&g_pmax[g * 32 + c], v);
    if (c == 0) atomicAdd(&g_cntf[g], 1.f);
}

__global__ void pool_final_kernel(float* __restrict__ out) {
    const int i = blockIdx.x * blockDim.x + threadIdx.x;
    if (i >= NG * 64) return;
    const int g = i / 64, c = i % 64;
    out[i] = (c < 32) ? g_psum[g * 32 + c] / g_cntf[g]
                      : g_pmax[g * 32 + (c - 32)];
}

// ---------------- launch ---------------------------------------------------
static inline int gridFor(long long n) { return (int)((n + TB - 1) / TB); }

extern "C" void kernel_launch(void* const* d_in, const int* in_sizes, int n_in,
                              void* d_out, int out_size) {
    const float* x     = (const float*)d_in[0];
    const int*   ei    = (const int*)d_in[1];
    const int*   batch = (const int*)d_in[2];
    const float *Wl1=(const float*)d_in[3],  *bl1=(const float*)d_in[4];
    const float *Wr1=(const float*)d_in[5],  *br1=(const float*)d_in[6];
    const float *att1=(const float*)d_in[7], *b1=(const float*)d_in[8];
    const float *Wl2=(const float*)d_in[9],  *bl2=(const float*)d_in[10];
    const float *Wr2=(const float*)d_in[11], *br2=(const float*)d_in[12];
    const float *att2=(const float*)d_in[13],*b2=(const float*)d_in[14];
    const float *Wl3=(const float*)d_in[15], *bl3=(const float*)d_in[16];
    const float *Wr3=(const float*)d_in[17], *br3=(const float*)d_in[18];
    const float *att3=(const float*)d_in[19],*b3=(const float*)d_in[20];

    float *p_xl, *p_xr, *p_h;
    cudaGetSymbolAddress((void**)&p_xl, g_xl);
    cudaGetSymbolAddress((void**)&p_xr, g_xr);
    cudaGetSymbolAddress((void**)&p_h,  g_h);

    const int gNodeWarp = gridFor((long long)NN * 32);
    const int gLin      = NN / 16;

    // ---- CSR (dst-indexed) build, reused by all 3 layers
    deg_init_kernel<<<gridFor(NN), TB>>>();
    deg_count_kernel<<<gridFor(NE), TB>>>(ei);
    scan_kernel<<<1, 1024>>>();
    fill_kernel<<<gridFor(ET), TB>>>(ei);

    // ---- layer 1: 8 -> 128 (H=2, C=64), concat
    linear_kernel<8, 128, 8><<<gLin, TB>>>(x, Wl1, bl1, p_xl);
    linear_kernel<8, 128, 8><<<gLin, TB>>>(x, Wr1, br1, p_xr);
    gat_fused128_kernel<<<gNodeWarp, TB>>>(att1, b1, p_h);

    // ---- layer 2: 128 -> 128 (H=2, C=64), concat
    linear_kernel<128, 128, 64><<<gLin, TB>>>(p_h, Wl2, bl2, p_xl);
    linear_kernel<128, 128, 64><<<gLin, TB>>>(p_h, Wr2, br2, p_xr);
    gat_fused128_kernel<<<gNodeWarp, TB>>>(att2, b2, p_h);

    // ---- layer 3: 128 -> 32 (H=1, C=32), head-mean (=identity)
    linear_kernel<128, 32, 64><<<gLin, TB>>>(p_h, Wl3, bl3, p_xl);
    linear_kernel<128, 32, 64><<<gLin, TB>>>(p_h, Wr3, br3, p_xr);
    gat_fused32_kernel<<<gNodeWarp, TB>>>(att3, b3, p_h);

    // ---- pooling: per-graph mean & max -> [16, 64]
    pool_init_kernel<<<gridFor(NG * 32), TB>>>();
    pool_accum_kernel<<<gNodeWarp, TB>>>(p_h, batch);
    pool_final_kernel<<<gridFor(NG * 64), TB>>>((float*)d_out);
}

// round 5
// speedup vs baseline: 2.6919x; 1.5968x over previous
#include <cuda_runtime.h>
#include <math.h>

// GATv2 x3 + pooling: CSR + online-softmax fused edge pass (ILP2),
// register-tiled linears.
namespace {
constexpr int NN = 50000;
constexpr int NE = 800000;
constexpr int ET = NE + NN;
constexpr int NG = 16;
constexpr int TB = 256;
}

// ---------------- scratch ---------------------------------------------------
__device__ __align__(16) float g_xl[(size_t)NN * 128];
__device__ __align__(16) float g_xr[(size_t)NN * 128];
__device__ __align__(16) float g_h[(size_t)NN * 128];
__device__ int g_deg[NN];
__device__ int g_rowptr[NN + 1];
__device__ int g_cur[NN];
__device__ int g_csrc[ET];
__device__ float g_psum[NG * 32];
__device__ float g_pmax[NG * 32];
__device__ float g_cntf[NG];

__device__ __forceinline__ void atomicMaxF(float* a, float v) {
    if (v >= 0.f) atomicMax((int*)a, __float_as_int(v));
    else          atomicMin((unsigned int*)a, __float_as_uint(v));
}

// ---------------- CSR build -------------------------------------------------
__global__ void deg_init_kernel() {
    int i = blockIdx.x * blockDim.x + threadIdx.x;
    if (i < NN) g_deg[i] = 1;            // self loop
}
__global__ void deg_count_kernel(const int* __restrict__ ei) {
    int e = blockIdx.x * blockDim.x + threadIdx.x;
    if (e < NE) atomicAdd(&g_deg[ei[NE + e]], 1);
}
__global__ void scan_kernel() {
    __shared__ int part[1024];
    const int tid = threadIdx.x;
    const int chunk = (NN + 1023) / 1024;
    const int beg = tid * chunk;
    const int end = min(beg + chunk, NN);
    int s = 0;
    for (int i = beg; i < end; i++) s += g_deg[i];
    part[tid] = s;
    __syncthreads();
    if (tid == 0) {
        int run = 0;
        for (int i = 0; i < 1024; i++) { int t = part[i]; part[i] = run; run += t; }
    }
    __syncthreads();
    int run = part[tid];
    for (int i = beg; i < end; i++) {
        g_rowptr[i] = run;
        g_cur[i] = run;
        run += g_deg[i];
    }
    if (tid == 0) g_rowptr[NN] = ET;
}
__global__ void fill_kernel(const int* __restrict__ ei) {
    int e = blockIdx.x * blockDim.x + threadIdx.x;
    if (e >= ET) return;
    int src, dst;
    if (e < NE) { src = ei[e]; dst = ei[NE + e]; }
    else        { src = e - NE; dst = src; }
    int pos = atomicAdd(&g_cur[dst], 1);
    g_csrc[pos] = src;
}

// ---------------- register-tiled linear: Y = X @ W + B ----------------------
// thread computes 4 nodes x 8 outputs; X and W k-tiles staged in SMEM.
template<int IN, int OUT>
__global__ __launch_bounds__(256)
void linear_rt_kernel(const float* __restrict__ X,
                      const float* __restrict__ W,
                      const float* __restrict__ B,
                      float* __restrict__ Y) {
    constexpr int TO  = OUT / 8;          // out groups
    constexpr int NGR = 256 / TO;         // node groups
    constexpr int NPB = NGR * 4;          // nodes per block
    constexpr int KT  = (IN < 32) ? IN : 32;

    __shared__ float Xs[KT][NPB + 4];
    __shared__ float Ws[KT][OUT];

    const int tid = threadIdx.x;
    const int og  = tid % TO;
    const int ng  = tid / TO;
    const int nb  = blockIdx.x * NPB;

    float acc[4][8];
#pragma unroll
    for (int i = 0; i < 4; i++) {
#pragma unroll
        for (int j = 0; j < 8; j++) acc[i][j] = 0.f;
    }

    for (int kt = 0; kt < IN; kt += KT) {
        __syncthreads();
        // stage W tile
        for (int idx = tid; idx < KT * OUT / 4; idx += 256) {
            const int k = idx / (OUT / 4), o4 = idx % (OUT / 4);
            ((float4*)Ws[k])[o4] =
                ((const float4*)(W + (size_t)(kt + k) * OUT))[o4];
        }
        // stage X tile (transposed)
        for (int idx = tid; idx < NPB * (KT / 4); idx += 256) {
            const int ni = idx / (KT / 4), f4 = idx % (KT / 4);
            const int gn = nb + ni;
            float4 xv = make_float4(0.f, 0.f, 0.f, 0.f);
            if (gn < NN)
                xv = ((const float4*)(X + (size_t)gn * IN + kt))[f4];
            Xs[f4 * 4 + 0][ni] = xv.x;
            Xs[f4 * 4 + 1][ni] = xv.y;
            Xs[f4 * 4 + 2][ni] = xv.z;
            Xs[f4 * 4 + 3][ni] = xv.w;
        }
        __syncthreads();
#pragma unroll
        for (int k = 0; k < KT; k++) {
            float xv[4];
#pragma unroll
            for (int i = 0; i < 4; i++) xv[i] = Xs[k][ng * 4 + i];
            const float4 w0 = ((const float4*)&Ws[k][og * 8])[0];
            const float4 w1 = ((const float4*)&Ws[k][og * 8])[1];
#pragma unroll
            for (int i = 0; i < 4; i++) {
                acc[i][0] += xv[i] * w0.x;
                acc[i][1] += xv[i] * w0.y;
                acc[i][2] += xv[i] * w0.z;
                acc[i][3] += xv[i] * w0.w;
                acc[i][4] += xv[i] * w1.x;
                acc[i][5] += xv[i] * w1.y;
                acc[i][6] += xv[i] * w1.z;
                acc[i][7] += xv[i] * w1.w;
            }
        }
    }

    const float4 b0 = ((const float4*)(B + og * 8))[0];
    const float4 b1 = ((const float4*)(B + og * 8))[1];
#pragma unroll
    for (int i = 0; i < 4; i++) {
        const int node = nb + ng * 4 + i;
        if (node >= NN) continue;
        float4 o0, o1;
        o0.x = acc[i][0] + b0.x; o0.y = acc[i][1] + b0.y;
        o0.z = acc[i][2] + b0.z; o0.w = acc[i][3] + b0.w;
        o1.x = acc[i][4] + b1.x; o1.y = acc[i][5] + b1.y;
        o1.z = acc[i][6] + b1.z; o1.w = acc[i][7] + b1.w;
        ((float4*)(Y + (size_t)node * OUT + og * 8))[0] = o0;
        ((float4*)(Y + (size_t)node * OUT + og * 8))[1] = o1;
    }
}

// ---------------- fused GATv2 edge pass (CT=128, H=2), warp per dst, ILP2 ---
__global__ void gat_fused128_kernel(const float* __restrict__ att,
                                    const float* __restrict__ B,
                                    float* __restrict__ out) {
    const int node = (blockIdx.x * blockDim.x + threadIdx.x) >> 5;
    if (node >= NN) return;
    const int lane = threadIdx.x & 31;

    const float4 xrv  = *(const float4*)(g_xr + (size_t)node * 128 + lane * 4);
    const float4 attv = *(const float4*)(att + lane * 4);

    int p  = g_rowptr[node];
    const int pe = g_rowptr[node + 1];

    float m0 = -INFINITY, d0 = 0.f, m1 = -INFINITY, d1 = 0.f;
    float4 A0 = make_float4(0.f, 0.f, 0.f, 0.f);
    float4 A1 = make_float4(0.f, 0.f, 0.f, 0.f);

    for (; p + 1 < pe; p += 2) {
        const int s0 = g_csrc[p];
        const int s1 = g_csrc[p + 1];
        const float4 a0 = *(const float4*)(g_xl + (size_t)s0 * 128 + lane * 4);
        const float4 a1 = *(const float4*)(g_xl + (size_t)s1 * 128 + lane * 4);

        float t, p0 = 0.f, p1 = 0.f;
        t = a0.x + xrv.x; t = t > 0.f ? t : 0.2f * t; p0 += t * attv.x;
        t = a1.x + xrv.x; t = t > 0.f ? t : 0.2f * t; p1 += t * attv.x;
        t = a0.y + xrv.y; t = t > 0.f ? t : 0.2f * t; p0 += t * attv.y;
        t = a1.y + xrv.y; t = t > 0.f ? t : 0.2f * t; p1 += t * attv.y;
        t = a0.z + xrv.z; t = t > 0.f ? t : 0.2f * t; p0 += t * attv.z;
        t = a1.z + xrv.z; t = t > 0.f ? t : 0.2f * t; p1 += t * attv.z;
        t = a0.w + xrv.w; t = t > 0.f ? t : 0.2f * t; p0 += t * attv.w;
        t = a1.w + xrv.w; t = t > 0.f ? t : 0.2f * t; p1 += t * attv.w;
#pragma unroll
        for (int off = 1; off <= 8; off <<= 1) {
            p0 += __shfl_xor_sync(0xffffffffu, p0, off);
            p1 += __shfl_xor_sync(0xffffffffu, p1, off);
        }
        // state 0 update
        {
            const float nm = fmaxf(m0, p0);
            const float sc = __expf(m0 - nm);
            const float w  = __expf(p0 - nm);
            d0 = d0 * sc + w;
            A0.x = A0.x * sc + w * a0.x;
            A0.y = A0.y * sc + w * a0.y;
            A0.z = A0.z * sc + w * a0.z;
            A0.w = A0.w * sc + w * a0.w;
            m0 = nm;
        }
        // state 1 update (independent)
        {
            const float nm = fmaxf(m1, p1);
            const float sc = __expf(m1 - nm);
            const float w  = __expf(p1 - nm);
            d1 = d1 * sc + w;
            A1.x = A1.x * sc + w * a1.x;
            A1.y = A1.y * sc + w * a1.y;
            A1.z = A1.z * sc + w * a1.z;
            A1.w = A1.w * sc + w * a1.w;
            m1 = nm;
        }
    }
    if (p < pe) {  // tail edge -> state 0
        const int s0 = g_csrc[p];
        const float4 a0 = *(const float4*)(g_xl + (size_t)s0 * 128 + lane * 4);
        float t, p0 = 0.f;
        t = a0.x + xrv.x; t = t > 0.f ? t : 0.2f * t; p0 += t * attv.x;
        t = a0.y + xrv.y; t = t > 0.f ? t : 0.2f * t; p0 += t * attv.y;
        t = a0.z + xrv.z; t = t > 0.f ? t : 0.2f * t; p0 += t * attv.z;
        t = a0.w + xrv.w; t = t > 0.f ? t : 0.2f * t; p0 += t * attv.w;
#pragma unroll
        for (int off = 1; off <= 8; off <<= 1)
            p0 += __shfl_xor_sync(0xffffffffu, p0, off);
        const float nm = fmaxf(m0, p0);
        const float sc = __expf(m0 - nm);
        const float w  = __expf(p0 - nm);
        d0 = d0 * sc + w;
        A0.x = A0.x * sc + w * a0.x;
        A0.y = A0.y * sc + w * a0.y;
        A0.z = A0.z * sc + w * a0.z;
        A0.w = A0.w * sc + w * a0.w;
        m0 = nm;
    }
    // merge states (m0 always finite: deg >= 1)
    const float M  = fmaxf(m0, m1);
    const float s0 = __expf(m0 - M);
    const float s1 = (m1 == -INFINITY) ? 0.f : __expf(m1 - M);
    const float d  = d0 * s0 + d1 * s1;
    float4 acc;
    acc.x = A0.x * s0 + A1.x * s1;
    acc.y = A0.y * s0 + A1.y * s1;
    acc.z = A0.z * s0 + A1.z * s1;
    acc.w = A0.w * s0 + A1.w * s1;

    const float inv = 1.f / (d + 1e-16f);
    const float4 bv = *(const float4*)(B + lane * 4);
    float4 o;
    o.x = acc.x * inv + bv.x; o.x = o.x > 0.f ? o.x : expm1f(o.x);
    o.y = acc.y * inv + bv.y; o.y = o.y > 0.f ? o.y : expm1f(o.y);
    o.z = acc.z * inv + bv.z; o.z = o.z > 0.f ? o.z : expm1f(o.z);
    o.w = acc.w * inv + bv.w; o.w = o.w > 0.f ? o.w : expm1f(o.w);
    *(float4*)(out + (size_t)node * 128 + lane * 4) = o;
}

// ---------------- fused GATv2 edge pass (CT=32, H=1), warp per dst, ILP2 ----
__global__ void gat_fused32_kernel(const float* __restrict__ att,
                                   const float* __restrict__ B,
                                   float* __restrict__ out) {
    const int node = (blockIdx.x * blockDim.x + threadIdx.x) >> 5;
    if (node >= NN) return;
    const int lane = threadIdx.x & 31;

    const float xrv  = g_xr[(size_t)node * 32 + lane];
    const float attv = att[lane];

    int p  = g_rowptr[node];
    const int pe = g_rowptr[node + 1];

    float m0 = -INFINITY, d0 = 0.f, acc0 = 0.f;
    float m1 = -INFINITY, d1 = 0.f, acc1 = 0.f;

    for (; p + 1 < pe; p += 2) {
        const int s0 = g_csrc[p];
        const int s1 = g_csrc[p + 1];
        const float a0 = g_xl[(size_t)s0 * 32 + lane];
        const float a1 = g_xl[(size_t)s1 * 32 + lane];

        float t0 = a0 + xrv; t0 = t0 > 0.f ? t0 : 0.2f * t0;
        float t1 = a1 + xrv; t1 = t1 > 0.f ? t1 : 0.2f * t1;
        float p0 = t0 * attv, p1 = t1 * attv;
#pragma unroll
        for (int off = 1; off <= 16; off <<= 1) {
            p0 += __shfl_xor_sync(0xffffffffu, p0, off);
            p1 += __shfl_xor_sync(0xffffffffu, p1, off);
        }
        {
            const float nm = fmaxf(m0, p0);
            const float sc = __expf(m0 - nm);
            const float w  = __expf(p0 - nm);
            d0 = d0 * sc + w; acc0 = acc0 * sc + w * a0; m0 = nm;
        }
        {
            const float nm = fmaxf(m1, p1);
            const float sc = __expf(m1 - nm);
            const float w  = __expf(p1 - nm);
            d1 = d1 * sc + w; acc1 = acc1 * sc + w * a1; m1 = nm;
        }
    }
    if (p < pe) {
        const int s0 = g_csrc[p];
        const float a0 = g_xl[(size_t)s0 * 32 + lane];
        float t0 = a0 + xrv; t0 = t0 > 0.f ? t0 : 0.2f * t0;
        float p0 = t0 * attv;
#pragma unroll
        for (int off = 1; off <= 16; off <<= 1)
            p0 += __shfl_xor_sync(0xffffffffu, p0, off);
        const float nm = fmaxf(m0, p0);
        const float sc = __expf(m0 - nm);
        const float w  = __expf(p0 - nm);
        d0 = d0 * sc + w; acc0 = acc0 * sc + w * a0; m0 = nm;
    }
    const float M  = fmaxf(m0, m1);
    const float s0 = __expf(m0 - M);
    const float s1 = (m1 == -INFINITY) ? 0.f : __expf(m1 - M);
    const float d  = d0 * s0 + d1 * s1;
    const float acc = acc0 * s0 + acc1 * s1;

    float o = acc / (d + 1e-16f) + B[lane];
    o = o > 0.f ? o : expm1f(o);
    out[(size_t)node * 32 + lane] = o;
}

// ---------------- pooling ----------------------------------------------------
__global__ void pool_init_kernel() {
    int i = blockIdx.x * blockDim.x + threadIdx.x;
    if (i < NG * 32) { g_psum[i] = 0.f; g_pmax[i] = -INFINITY; }
    if (i < NG) g_cntf[i] = 0.f;
}
__global__ void pool_accum_kernel(const float* __restrict__ h,
                                  const int* __restrict__ batch) {
    const int i = blockIdx.x * blockDim.x + threadIdx.x;
    if (i >= NN * 32) return;
    const int node = i >> 5, c = i & 31;
    const int g = batch[node];
    const float v = h[i];
    atomicAdd(&g_psum[g * 32 + c], v);
    atomicMaxF(&g_pmax[g * 32 + c], v);
    if (c == 0) atomicAdd(&g_cntf[g], 1.f);
}
__global__ void pool_final_kernel(float* __restrict__ out) {
    const int i = blockIdx.x * blockDim.x + threadIdx.x;
    if (i >= NG * 64) return;
    const int g = i / 64, c = i % 64;
    out[i] = (c < 32) ? g_psum[g * 32 + c] / g_cntf[g]
                      : g_pmax[g * 32 + (c - 32)];
}

// ---------------- launch ------------------------------------------------------
static inline int gridFor(long long n) { return (int)((n + TB - 1) / TB); }

extern "C" void kernel_launch(void* const* d_in, const int* in_sizes, int n_in,
                              void* d_out, int out_size) {
    const float* x     = (const float*)d_in[0];
    const int*   ei    = (const int*)d_in[1];
    const int*   batch = (const int*)d_in[2];
    const float *Wl1=(const float*)d_in[3],  *bl1=(const float*)d_in[4];
    const float *Wr1=(const float*)d_in[5],  *br1=(const float*)d_in[6];
    const float *att1=(const float*)d_in[7], *b1=(const float*)d_in[8];
    const float *Wl2=(const float*)d_in[9],  *bl2=(const float*)d_in[10];
    const float *Wr2=(const float*)d_in[11], *br2=(const float*)d_in[12];
    const float *att2=(const float*)d_in[13],*b2=(const float*)d_in[14];
    const float *Wl3=(const float*)d_in[15], *bl3=(const float*)d_in[16];
    const float *Wr3=(const float*)d_in[17], *br3=(const float*)d_in[18];
    const float *att3=(const float*)d_in[19],*b3=(const float*)d_in[20];

    float *p_xl, *p_xr, *p_h;
    cudaGetSymbolAddress((void**)&p_xl, g_xl);
    cudaGetSymbolAddress((void**)&p_xr, g_xr);
    cudaGetSymbolAddress((void**)&p_h,  g_h);

    const int gNodeWarp = gridFor((long long)NN * 32);
    const int gLin128   = (NN + 63) / 64;    // NPB=64 for OUT=128
    const int gLin32    = (NN + 255) / 256;  // NPB=256 for OUT=32

    // ---- CSR (dst-indexed) build, reused by all 3 layers
    deg_init_kernel<<<gridFor(NN), TB>>>();
    deg_count_kernel<<<gridFor(NE), TB>>>(ei);
    scan_kernel<<<1, 1024>>>();
    fill_kernel<<<gridFor(ET), TB>>>(ei);

    // ---- layer 1: 8 -> 128 (H=2, C=64)
    linear_rt_kernel<8, 128><<<gLin128, 256>>>(x, Wl1, bl1, p_xl);
    linear_rt_kernel<8, 128><<<gLin128, 256>>>(x, Wr1, br1, p_xr);
    gat_fused128_kernel<<<gNodeWarp, TB>>>(att1, b1, p_h);

    // ---- layer 2: 128 -> 128 (H=2, C=64)
    linear_rt_kernel<128, 128><<<gLin128, 256>>>(p_h, Wl2, bl2, p_xl);
    linear_rt_kernel<128, 128><<<gLin128, 256>>>(p_h, Wr2, br2, p_xr);
    gat_fused128_kernel<<<gNodeWarp, TB>>>(att2, b2, p_h);

    // ---- layer 3: 128 -> 32 (H=1, C=32)
    linear_rt_kernel<128, 32><<<gLin32, 256>>>(p_h, Wl3, bl3, p_xl);
    linear_rt_kernel<128, 32><<<gLin32, 256>>>(p_h, Wr3, br3, p_xr);
    gat_fused32_kernel<<<gNodeWarp, TB>>>(att3, b3, p_h);

    // ---- pooling
    pool_init_kernel<<<gridFor(NG * 32), TB>>>();
    pool_accum_kernel<<<gNodeWarp, TB>>>(p_h, batch);
    pool_final_kernel<<<gridFor(NG * 64), TB>>>((float*)d_out);
}

// round 6
// speedup vs baseline: 3.3095x; 1.2294x over previous
#include <cuda_runtime.h>
#include <math.h>

// GATv2 x3 + pooling: CSR + ILP4 online-softmax fused edge pass,
// dual (Wl+Wr) register-tiled linears, SMEM-staged pooling.
namespace {
constexpr int NN = 50000;
constexpr int NE = 800000;
constexpr int ET = NE + NN;
constexpr int NG = 16;
constexpr int TB = 256;
}

// ---------------- scratch ---------------------------------------------------
__device__ __align__(16) float g_xl[(size_t)NN * 128];
__device__ __align__(16) float g_xr[(size_t)NN * 128];
__device__ __align__(16) float g_h[(size_t)NN * 128];
__device__ int g_deg[NN];
__device__ int g_rowptr[NN + 1];
__device__ int g_cur[NN];
__device__ int g_csrc[ET];
__device__ float g_psum[NG * 32];
__device__ float g_pmax[NG * 32];
__device__ float g_cntf[NG];

__device__ __forceinline__ void atomicMaxF(float* a, float v) {
    if (v >= 0.f) atomicMax((int*)a, __float_as_int(v));
    else          atomicMin((unsigned int*)a, __float_as_uint(v));
}

// ---------------- CSR build -------------------------------------------------
__global__ void deg_init_kernel() {
    int i = blockIdx.x * blockDim.x + threadIdx.x;
    if (i < NN) g_deg[i] = 1;            // self loop
}
__global__ void deg_count_kernel(const int* __restrict__ ei) {
    int e = blockIdx.x * blockDim.x + threadIdx.x;
    if (e < NE) atomicAdd(&g_deg[ei[NE + e]], 1);
}
__global__ void scan_kernel() {
    __shared__ int part[1024];
    const int tid = threadIdx.x;
    const int chunk = (NN + 1023) / 1024;
    const int beg = tid * chunk;
    const int end = min(beg + chunk, NN);
    int s = 0;
    for (int i = beg; i < end; i++) s += g_deg[i];
    part[tid] = s;
    __syncthreads();
    if (tid == 0) {
        int run = 0;
        for (int i = 0; i < 1024; i++) { int t = part[i]; part[i] = run; run += t; }
    }
    __syncthreads();
    int run = part[tid];
    for (int i = beg; i < end; i++) {
        g_rowptr[i] = run;
        g_cur[i] = run;
        run += g_deg[i];
    }
    if (tid == 0) g_rowptr[NN] = ET;
}
__global__ void fill_kernel(const int* __restrict__ ei) {
    int e = blockIdx.x * blockDim.x + threadIdx.x;
    if (e >= ET) return;
    int src, dst;
    if (e < NE) { src = ei[e]; dst = ei[NE + e]; }
    else        { src = e - NE; dst = src; }
    int pos = atomicAdd(&g_cur[dst], 1);
    g_csrc[pos] = src;
}

// ---------------- dual linear: Yl = X@Wl+Bl, Yr = X@Wr+Br -------------------
// thread computes 4 nodes x 8 outputs x 2 matrices; tiles staged in SMEM.
template<int IN, int OUT>
__global__ __launch_bounds__(256)
void linear_dual_kernel(const float* __restrict__ X,
                        const float* __restrict__ Wl, const float* __restrict__ Bl,
                        const float* __restrict__ Wr, const float* __restrict__ Br,
                        float* __restrict__ Yl, float* __restrict__ Yr) {
    constexpr int TO  = OUT / 8;
    constexpr int NGR = 256 / TO;
    constexpr int NPB = NGR * 4;
    constexpr int KT  = (IN < 32) ? IN : 32;

    __shared__ float Xs[KT][NPB + 4];
    __shared__ float Wsl[KT][OUT];
    __shared__ float Wsr[KT][OUT];

    const int tid = threadIdx.x;
    const int og  = tid % TO;
    const int ng  = tid / TO;
    const int nb  = blockIdx.x * NPB;

    float accl[4][8], accr[4][8];
#pragma unroll
    for (int i = 0; i < 4; i++)
#pragma unroll
        for (int j = 0; j < 8; j++) { accl[i][j] = 0.f; accr[i][j] = 0.f; }

    for (int kt = 0; kt < IN; kt += KT) {
        __syncthreads();
        for (int idx = tid; idx < KT * OUT / 4; idx += 256) {
            const int k = idx / (OUT / 4), o4 = idx % (OUT / 4);
            ((float4*)Wsl[k])[o4] = ((const float4*)(Wl + (size_t)(kt + k) * OUT))[o4];
            ((float4*)Wsr[k])[o4] = ((const float4*)(Wr + (size_t)(kt + k) * OUT))[o4];
        }
        for (int idx = tid; idx < NPB * (KT / 4); idx += 256) {
            const int ni = idx / (KT / 4), f4 = idx % (KT / 4);
            const int gn = nb + ni;
            float4 xv = make_float4(0.f, 0.f, 0.f, 0.f);
            if (gn < NN)
                xv = ((const float4*)(X + (size_t)gn * IN + kt))[f4];
            Xs[f4 * 4 + 0][ni] = xv.x;
            Xs[f4 * 4 + 1][ni] = xv.y;
            Xs[f4 * 4 + 2][ni] = xv.z;
            Xs[f4 * 4 + 3][ni] = xv.w;
        }
        __syncthreads();
#pragma unroll
        for (int k = 0; k < KT; k++) {
            float xv[4];
#pragma unroll
            for (int i = 0; i < 4; i++) xv[i] = Xs[k][ng * 4 + i];
            const float4 wl0 = ((const float4*)&Wsl[k][og * 8])[0];
            const float4 wl1 = ((const float4*)&Wsl[k][og * 8])[1];
            const float4 wr0 = ((const float4*)&Wsr[k][og * 8])[0];
            const float4 wr1 = ((const float4*)&Wsr[k][og * 8])[1];
#pragma unroll
            for (int i = 0; i < 4; i++) {
                accl[i][0] += xv[i] * wl0.x; accl[i][1] += xv[i] * wl0.y;
                accl[i][2] += xv[i] * wl0.z; accl[i][3] += xv[i] * wl0.w;
                accl[i][4] += xv[i] * wl1.x; accl[i][5] += xv[i] * wl1.y;
                accl[i][6] += xv[i] * wl1.z; accl[i][7] += xv[i] * wl1.w;
                accr[i][0] += xv[i] * wr0.x; accr[i][1] += xv[i] * wr0.y;
                accr[i][2] += xv[i] * wr0.z; accr[i][3] += xv[i] * wr0.w;
                accr[i][4] += xv[i] * wr1.x; accr[i][5] += xv[i] * wr1.y;
                accr[i][6] += xv[i] * wr1.z; accr[i][7] += xv[i] * wr1.w;
            }
        }
    }

    const float4 bl0 = ((const float4*)(Bl + og * 8))[0];
    const float4 bl1 = ((const float4*)(Bl + og * 8))[1];
    const float4 br0 = ((const float4*)(Br + og * 8))[0];
    const float4 br1 = ((const float4*)(Br + og * 8))[1];
#pragma unroll
    for (int i = 0; i < 4; i++) {
        const int node = nb + ng * 4 + i;
        if (node >= NN) continue;
        float4 o;
        o = make_float4(accl[i][0]+bl0.x, accl[i][1]+bl0.y, accl[i][2]+bl0.z, accl[i][3]+bl0.w);
        ((float4*)(Yl + (size_t)node * OUT + og * 8))[0] = o;
        o = make_float4(accl[i][4]+bl1.x, accl[i][5]+bl1.y, accl[i][6]+bl1.z, accl[i][7]+bl1.w);
        ((float4*)(Yl + (size_t)node * OUT + og * 8))[1] = o;
        o = make_float4(accr[i][0]+br0.x, accr[i][1]+br0.y, accr[i][2]+br0.z, accr[i][3]+br0.w);
        ((float4*)(Yr + (size_t)node * OUT + og * 8))[0] = o;
        o = make_float4(accr[i][4]+br1.x, accr[i][5]+br1.y, accr[i][6]+br1.z, accr[i][7]+br1.w);
        ((float4*)(Yr + (size_t)node * OUT + og * 8))[1] = o;
    }
}

// ---------------- fused GATv2 edge pass (CT=128, H=2), warp/dst, ILP4 -------
__global__ void gat_fused128_kernel(const float* __restrict__ att,
                                    const float* __restrict__ B,
                                    float* __restrict__ out) {
    const int node = (blockIdx.x * blockDim.x + threadIdx.x) >> 5;
    if (node >= NN) return;
    const int lane = threadIdx.x & 31;

    const float4 xrv  = *(const float4*)(g_xr + (size_t)node * 128 + lane * 4);
    const float4 attv = *(const float4*)(att + lane * 4);

    int p  = g_rowptr[node];
    const int pe = g_rowptr[node + 1];

    float  m[4] = {-INFINITY, -INFINITY, -INFINITY, -INFINITY};
    float  dd[4] = {0.f, 0.f, 0.f, 0.f};
    float4 A[4];
#pragma unroll
    for (int j = 0; j < 4; j++) A[j] = make_float4(0.f, 0.f, 0.f, 0.f);

    for (; p + 3 < pe; p += 4) {
        int s[4];
#pragma unroll
        for (int j = 0; j < 4; j++) s[j] = g_csrc[p + j];
        float4 a[4];
#pragma unroll
        for (int j = 0; j < 4; j++)
            a[j] = *(const float4*)(g_xl + (size_t)s[j] * 128 + lane * 4);

        float pp[4];
#pragma unroll
        for (int j = 0; j < 4; j++) {
            float t, sc = 0.f;
            t = a[j].x + xrv.x; t = t > 0.f ? t : 0.2f * t; sc += t * attv.x;
            t = a[j].y + xrv.y; t = t > 0.f ? t : 0.2f * t; sc += t * attv.y;
            t = a[j].z + xrv.z; t = t > 0.f ? t : 0.2f * t; sc += t * attv.z;
            t = a[j].w + xrv.w; t = t > 0.f ? t : 0.2f * t; sc += t * attv.w;
            pp[j] = sc;
        }
#pragma unroll
        for (int off = 1; off <= 8; off <<= 1)
#pragma unroll
            for (int j = 0; j < 4; j++)
                pp[j] += __shfl_xor_sync(0xffffffffu, pp[j], off);
#pragma unroll
        for (int j = 0; j < 4; j++) {
            const float nm = fmaxf(m[j], pp[j]);
            const float sc = __expf(m[j] - nm);
            const float w  = __expf(pp[j] - nm);
            dd[j] = dd[j] * sc + w;
            A[j].x = A[j].x * sc + w * a[j].x;
            A[j].y = A[j].y * sc + w * a[j].y;
            A[j].z = A[j].z * sc + w * a[j].z;
            A[j].w = A[j].w * sc + w * a[j].w;
            m[j] = nm;
        }
    }
    for (; p < pe; ++p) {   // tail -> state 0
        const int s0 = g_csrc[p];
        const float4 a0 = *(const float4*)(g_xl + (size_t)s0 * 128 + lane * 4);
        float t, p0 = 0.f;
        t = a0.x + xrv.x; t = t > 0.f ? t : 0.2f * t; p0 += t * attv.x;
        t = a0.y + xrv.y; t = t > 0.f ? t : 0.2f * t; p0 += t * attv.y;
        t = a0.z + xrv.z; t = t > 0.f ? t : 0.2f * t; p0 += t * attv.z;
        t = a0.w + xrv.w; t = t > 0.f ? t : 0.2f * t; p0 += t * attv.w;
#pragma unroll
        for (int off = 1; off <= 8; off <<= 1)
            p0 += __shfl_xor_sync(0xffffffffu, p0, off);
        const float nm = fmaxf(m[0], p0);
        const float sc = __expf(m[0] - nm);
        const float w  = __expf(p0 - nm);
        dd[0] = dd[0] * sc + w;
        A[0].x = A[0].x * sc + w * a0.x;
        A[0].y = A[0].y * sc + w * a0.y;
        A[0].z = A[0].z * sc + w * a0.z;
        A[0].w = A[0].w * sc + w * a0.w;
        m[0] = nm;
    }
    // merge 4 states (m[0] always finite: deg >= 1)
    float M = fmaxf(fmaxf(m[0], m[1]), fmaxf(m[2], m[3]));
    float d = 0.f;
    float4 acc = make_float4(0.f, 0.f, 0.f, 0.f);
#pragma unroll
    for (int j = 0; j < 4; j++) {
        const float sj = (m[j] == -INFINITY) ? 0.f : __expf(m[j] - M);
        d += dd[j] * sj;
        acc.x += A[j].x * sj; acc.y += A[j].y * sj;
        acc.z += A[j].z * sj; acc.w += A[j].w * sj;
    }

    const float inv = 1.f / (d + 1e-16f);
    const float4 bv = *(const float4*)(B + lane * 4);
    float4 o;
    o.x = acc.x * inv + bv.x; o.x = o.x > 0.f ? o.x : expm1f(o.x);
    o.y = acc.y * inv + bv.y; o.y = o.y > 0.f ? o.y : expm1f(o.y);
    o.z = acc.z * inv + bv.z; o.z = o.z > 0.f ? o.z : expm1f(o.z);
    o.w = acc.w * inv + bv.w; o.w = o.w > 0.f ? o.w : expm1f(o.w);
    *(float4*)(out + (size_t)node * 128 + lane * 4) = o;
}

// ---------------- fused GATv2 edge pass (CT=32, H=1), warp/dst, ILP4 --------
__global__ void gat_fused32_kernel(const float* __restrict__ att,
                                   const float* __restrict__ B,
                                   float* __restrict__ out) {
    const int node = (blockIdx.x * blockDim.x + threadIdx.x) >> 5;
    if (node >= NN) return;
    const int lane = threadIdx.x & 31;

    const float xrv  = g_xr[(size_t)node * 32 + lane];
    const float attv = att[lane];

    int p  = g_rowptr[node];
    const int pe = g_rowptr[node + 1];

    float m[4] = {-INFINITY, -INFINITY, -INFINITY, -INFINITY};
    float dd[4] = {0.f, 0.f, 0.f, 0.f};
    float A[4] = {0.f, 0.f, 0.f, 0.f};

    for (; p + 3 < pe; p += 4) {
        float a[4], pp[4];
#pragma unroll
        for (int j = 0; j < 4; j++) {
            const int s = g_csrc[p + j];
            a[j] = g_xl[(size_t)s * 32 + lane];
            float t = a[j] + xrv; t = t > 0.f ? t : 0.2f * t;
            pp[j] = t * attv;
        }
#pragma unroll
        for (int off = 1; off <= 16; off <<= 1)
#pragma unroll
            for (int j = 0; j < 4; j++)
                pp[j] += __shfl_xor_sync(0xffffffffu, pp[j], off);
#pragma unroll
        for (int j = 0; j < 4; j++) {
            const float nm = fmaxf(m[j], pp[j]);
            const float sc = __expf(m[j] - nm);
            const float w  = __expf(pp[j] - nm);
            dd[j] = dd[j] * sc + w; A[j] = A[j] * sc + w * a[j]; m[j] = nm;
        }
    }
    for (; p < pe; ++p) {
        const int s = g_csrc[p];
        const float a0 = g_xl[(size_t)s * 32 + lane];
        float t = a0 + xrv; t = t > 0.f ? t : 0.2f * t;
        float p0 = t * attv;
#pragma unroll
        for (int off = 1; off <= 16; off <<= 1)
            p0 += __shfl_xor_sync(0xffffffffu, p0, off);
        const float nm = fmaxf(m[0], p0);
        const float sc = __expf(m[0] - nm);
        const float w  = __expf(p0 - nm);
        dd[0] = dd[0] * sc + w; A[0] = A[0] * sc + w * a0; m[0] = nm;
    }
    float M = fmaxf(fmaxf(m[0], m[1]), fmaxf(m[2], m[3]));
    float d = 0.f, acc = 0.f;
#pragma unroll
    for (int j = 0; j < 4; j++) {
        const float sj = (m[j] == -INFINITY) ? 0.f : __expf(m[j] - M);
        d += dd[j] * sj; acc += A[j] * sj;
    }

    float o = acc / (d + 1e-16f) + B[lane];
    o = o > 0.f ? o : expm1f(o);
    out[(size_t)node * 32 + lane] = o;
}

// ---------------- pooling ----------------------------------------------------
__global__ void pool_init_kernel() {
    int i = blockIdx.x * blockDim.x + threadIdx.x;
    if (i < NG * 32) { g_psum[i] = 0.f; g_pmax[i] = -INFINITY; }
    if (i < NG) g_cntf[i] = 0.f;
}

// block = 256 threads = 8 warps; warp w handles nodes [blk*256 + w*32 .. +31],
// lane l owns channel l -> conflict-free smem atomics.
__global__ __launch_bounds__(256)
void pool_accum_kernel(const float* __restrict__ h,
                       const int* __restrict__ batch) {
    __shared__ float ssum[NG * 32];
    __shared__ float smax[NG * 32];
    __shared__ int   scnt[NG];
    const int tid = threadIdx.x;
    for (int i = tid; i < NG * 32; i += 256) { ssum[i] = 0.f; smax[i] = -INFINITY; }
    if (tid < NG) scnt[tid] = 0;
    __syncthreads();

    const int warp = tid >> 5, lane = tid & 31;
    const int nbase = blockIdx.x * 256 + warp * 32;
#pragma unroll 4
    for (int i = 0; i < 32; i++) {
        const int node = nbase + i;
        if (node >= NN) break;
        const int g = batch[node];
        const float v = h[(size_t)node * 32 + lane];
        atomicAdd(&ssum[g * 32 + lane], v);
        atomicMaxF(&smax[g * 32 + lane], v);
        if (lane == 0) atomicAdd(&scnt[g], 1);
    }
    __syncthreads();

    for (int i = tid; i < NG * 32; i += 256) {
        if (ssum[i] != 0.f) atomicAdd(&g_psum[i], ssum[i]);
        if (smax[i] != -INFINITY) atomicMaxF(&g_pmax[i], smax[i]);
    }
    if (tid < NG && scnt[tid] > 0) atomicAdd(&g_cntf[tid], (float)scnt[tid]);
}

__global__ void pool_final_kernel(float* __restrict__ out) {
    const int i = blockIdx.x * blockDim.x + threadIdx.x;
    if (i >= NG * 64) return;
    const int g = i / 64, c = i % 64;
    out[i] = (c < 32) ? g_psum[g * 32 + c] / g_cntf[g]
                      : g_pmax[g * 32 + (c - 32)];
}

// ---------------- launch ------------------------------------------------------
static inline int gridFor(long long n) { return (int)((n + TB - 1) / TB); }

extern "C" void kernel_launch(void* const* d_in, const int* in_sizes, int n_in,
                              void* d_out, int out_size) {
    const float* x     = (const float*)d_in[0];
    const int*   ei    = (const int*)d_in[1];
    const int*   batch = (const int*)d_in[2];
    const float *Wl1=(const float*)d_in[3],  *bl1=(const float*)d_in[4];
    const float *Wr1=(const float*)d_in[5],  *br1=(const float*)d_in[6];
    const float *att1=(const float*)d_in[7], *b1=(const float*)d_in[8];
    const float *Wl2=(const float*)d_in[9],  *bl2=(const float*)d_in[10];
    const float *Wr2=(const float*)d_in[11], *br2=(const float*)d_in[12];
    const float *att2=(const float*)d_in[13],*b2=(const float*)d_in[14];
    const float *Wl3=(const float*)d_in[15], *bl3=(const float*)d_in[16];
    const float *Wr3=(const float*)d_in[17], *br3=(const float*)d_in[18];
    const float *att3=(const float*)d_in[19],*b3=(const float*)d_in[20];

    float *p_xl, *p_xr, *p_h;
    cudaGetSymbolAddress((void**)&p_xl, g_xl);
    cudaGetSymbolAddress((void**)&p_xr, g_xr);
    cudaGetSymbolAddress((void**)&p_h,  g_h);

    const int gNodeWarp = gridFor((long long)NN * 32);
    const int gLin128   = (NN + 63) / 64;    // NPB=64 for OUT=128
    const int gLin32    = (NN + 255) / 256;  // NPB=256 for OUT=32
    const int gPool     = (NN + 255) / 256;

    // ---- CSR (dst-indexed) build, reused by all 3 layers
    deg_init_kernel<<<gridFor(NN), TB>>>();
    deg_count_kernel<<<gridFor(NE), TB>>>(ei);
    scan_kernel<<<1, 1024>>>();
    fill_kernel<<<gridFor(ET), TB>>>(ei);

    // ---- layer 1: 8 -> 128 (H=2, C=64)
    linear_dual_kernel<8, 128><<<gLin128, 256>>>(x, Wl1, bl1, Wr1, br1, p_xl, p_xr);
    gat_fused128_kernel<<<gNodeWarp, TB>>>(att1, b1, p_h);

    // ---- layer 2: 128 -> 128 (H=2, C=64)
    linear_dual_kernel<128, 128><<<gLin128, 256>>>(p_h, Wl2, bl2, Wr2, br2, p_xl, p_xr);
    gat_fused128_kernel<<<gNodeWarp, TB>>>(att2, b2, p_h);

    // ---- layer 3: 128 -> 32 (H=1, C=32)
    linear_dual_kernel<128, 32><<<gLin32, 256>>>(p_h, Wl3, bl3, Wr3, br3, p_xl, p_xr);
    gat_fused32_kernel<<<gNodeWarp, TB>>>(att3, b3, p_h);

    // ---- pooling
    pool_init_kernel<<<gridFor(NG * 32), TB>>>();
    pool_accum_kernel<<<gPool, 256>>>(p_h, batch);
    pool_final_kernel<<<gridFor(NG * 64), TB>>>((float*)d_out);
}